// round 3
// baseline (speedup 1.0000x reference)
#include <cuda_runtime.h>
#include <cstdint>

// Flag: 1 if idx buffer is int64, 0 if int32. Written by detect_kernel,
// read by the main kernel. __device__ global => allocation-free.
__device__ int g_idx_is64;

// Detect idx dtype. For int64 indices in [0, 1e6), the high 32-bit word of
// every entry is 0. For int32 indices, the "odd words" are themselves random
// indices and are ~never all zero across 64 entries.
__global__ void detect_idx_kernel(const unsigned int* __restrict__ idx_words) {
    int is64 = 1;
    #pragma unroll 1
    for (int k = 0; k < 64; ++k) {
        if (idx_words[2 * k + 1] != 0u) { is64 = 0; break; }
    }
    g_idx_is64 = is64;
}

// One neuron per 16 threads. lane = element index d in [0,16).
//   s[d]  = sum_k values[idx[n,k]*16 + d]          (coalesced 64B gathers)
//   y[d]  = b[n,d] + sum_j W[n,d,j] * s[j]         (s[j] via shfl width 16)
//   out   = tanh(y)
__global__ __launch_bounds__(256)
void weighted_atom_kernel(const float* __restrict__ values,
                          const void*  __restrict__ idx_raw,
                          const float* __restrict__ W,
                          const float* __restrict__ bvec,
                          float* __restrict__ out,
                          int N)
{
    const int gid  = blockIdx.x * blockDim.x + threadIdx.x;
    const int n    = gid >> 4;
    const int lane = gid & 15;
    if (n >= N) return;   // grid is sized exactly; never taken (keeps shfl safe)

    // ---- fetch the 8 fan-in row indices (uniform across the 16-lane group) ----
    long long rows[8];
    if (g_idx_is64) {
        const long long* idx = (const long long*)idx_raw;
        const long long* p = idx + (long long)n * 8;
        #pragma unroll
        for (int k = 0; k < 8; ++k) rows[k] = p[k];
    } else {
        const int* idx = (const int*)idx_raw;
        const int* p = idx + n * 8;
        #pragma unroll
        for (int k = 0; k < 8; ++k) rows[k] = p[k];
    }

    // ---- gather + fan-in sum: lane d owns element d ----
    float s = 0.0f;
    #pragma unroll
    for (int k = 0; k < 8; ++k) {
        s += __ldg(values + rows[k] * 16 + lane);
    }

    // ---- per-neuron linear: lane d owns output row d of W_n ----
    const float4* Wrow4 = (const float4*)(W + (size_t)n * 256 + (size_t)lane * 16);
    float4 w0 = Wrow4[0];
    float4 w1 = Wrow4[1];
    float4 w2 = Wrow4[2];
    float4 w3 = Wrow4[3];

    float y = bvec[gid];   // b[n*16 + lane] == b[gid]

    const unsigned mask = 0xFFFFFFFFu;
    y += w0.x * __shfl_sync(mask, s,  0, 16);
    y += w0.y * __shfl_sync(mask, s,  1, 16);
    y += w0.z * __shfl_sync(mask, s,  2, 16);
    y += w0.w * __shfl_sync(mask, s,  3, 16);
    y += w1.x * __shfl_sync(mask, s,  4, 16);
    y += w1.y * __shfl_sync(mask, s,  5, 16);
    y += w1.z * __shfl_sync(mask, s,  6, 16);
    y += w1.w * __shfl_sync(mask, s,  7, 16);
    y += w2.x * __shfl_sync(mask, s,  8, 16);
    y += w2.y * __shfl_sync(mask, s,  9, 16);
    y += w2.z * __shfl_sync(mask, s, 10, 16);
    y += w2.w * __shfl_sync(mask, s, 11, 16);
    y += w3.x * __shfl_sync(mask, s, 12, 16);
    y += w3.y * __shfl_sync(mask, s, 13, 16);
    y += w3.z * __shfl_sync(mask, s, 14, 16);
    y += w3.w * __shfl_sync(mask, s, 15, 16);

    out[gid] = tanhf(y);
}

extern "C" void kernel_launch(void* const* d_in, const int* in_sizes, int n_in,
                              void* d_out, int out_size)
{
    // metadata order == setup_inputs order: values, idx, W, b
    const float* values = (const float*)d_in[0];
    const void*  idx    = d_in[1];
    const float* W      = (const float*)d_in[2];
    const float* bvec   = (const float*)d_in[3];
    float* out          = (float*)d_out;

    const int N = in_sizes[3] / 16;   // b has N*16 elements

    detect_idx_kernel<<<1, 1>>>((const unsigned int*)idx);

    const int threads = 256;
    const int total   = N * 16;
    const int blocks  = (total + threads - 1) / threads;
    weighted_atom_kernel<<<blocks, threads>>>(values, idx, W, bvec, out, N);
}

// round 5
// speedup vs baseline: 1.1603x; 1.1603x over previous
#include <cuda_runtime.h>
#include <cstdint>

// Flag: 1 if idx buffer is int64, 0 if int32.
__device__ int g_idx_is64;

// Detect idx dtype: for int64 indices in [0, 1e6) the high words are all 0;
// for random int32 indices the odd words are ~never all zero across 64 entries.
__global__ void detect_idx_kernel(const unsigned int* __restrict__ idx_words) {
    int is64 = 1;
    #pragma unroll 1
    for (int k = 0; k < 64; ++k) {
        if (idx_words[2 * k + 1] != 0u) { is64 = 0; break; }
    }
    g_idx_is64 = is64;
}

// L2 access policy: evict_last (keep resident). Built once per thread.
__device__ __forceinline__ unsigned long long make_evict_last_policy() {
    unsigned long long pol;
    asm volatile("createpolicy.fractional.L2::evict_last.b64 %0, 1.0;" : "=l"(pol));
    return pol;
}

// values gather with L2-resident cache hint (legal scalar form on sm_103a).
__device__ __forceinline__ float ldg_L2_resident(const float* p, unsigned long long pol) {
    float v;
    asm volatile("ld.global.nc.L2::cache_hint.f32 %0, [%1], %2;"
                 : "=f"(v) : "l"(p), "l"(pol));
    return v;
}

// One neuron per 16 threads. lane = element index d in [0,16).
//   s[d]  = sum_k values[idx[n,k]*16 + d]          (coalesced 64B gathers, L2-pinned)
//   y[d]  = b[n,d] + sum_j W[n,d,j] * s[j]         (s[j] via shfl width 16)
//   out   = tanh(y)
// W/b are streamed with evict-first so they never displace values in L2.
__global__ __launch_bounds__(256)
void weighted_atom_kernel(const float* __restrict__ values,
                          const void*  __restrict__ idx_raw,
                          const float* __restrict__ W,
                          const float* __restrict__ bvec,
                          float* __restrict__ out,
                          int N)
{
    const int gid  = blockIdx.x * blockDim.x + threadIdx.x;
    const int n    = gid >> 4;
    const int lane = gid & 15;
    if (n >= N) return;   // grid sized exactly; never taken (keeps shfl safe)

    const unsigned long long pol = make_evict_last_policy();

    // ---- fetch the 8 fan-in row indices (uniform across the 16-lane group) ----
    long long rows[8];
    if (g_idx_is64) {
        const long long* p = (const long long*)idx_raw + (long long)n * 8;
        #pragma unroll
        for (int k = 0; k < 8; ++k) rows[k] = p[k];
    } else {
        const int* p = (const int*)idx_raw + n * 8;
        #pragma unroll
        for (int k = 0; k < 8; ++k) rows[k] = p[k];
    }

    // ---- streaming loads of W first (maximize MLP; evict-first in L2) ----
    const float4* Wrow4 = (const float4*)(W + (size_t)n * 256 + (size_t)lane * 16);
    float4 w0 = __ldcs(Wrow4 + 0);
    float4 w1 = __ldcs(Wrow4 + 1);
    float4 w2 = __ldcs(Wrow4 + 2);
    float4 w3 = __ldcs(Wrow4 + 3);
    float  y  = __ldcs(bvec + gid);   // b[n*16 + lane]

    // ---- gather + fan-in sum: lane d owns element d; pinned in L2 ----
    float s = 0.0f;
    #pragma unroll
    for (int k = 0; k < 8; ++k) {
        s += ldg_L2_resident(values + rows[k] * 16 + lane, pol);
    }

    const unsigned mask = 0xFFFFFFFFu;
    y += w0.x * __shfl_sync(mask, s,  0, 16);
    y += w0.y * __shfl_sync(mask, s,  1, 16);
    y += w0.z * __shfl_sync(mask, s,  2, 16);
    y += w0.w * __shfl_sync(mask, s,  3, 16);
    y += w1.x * __shfl_sync(mask, s,  4, 16);
    y += w1.y * __shfl_sync(mask, s,  5, 16);
    y += w1.z * __shfl_sync(mask, s,  6, 16);
    y += w1.w * __shfl_sync(mask, s,  7, 16);
    y += w2.x * __shfl_sync(mask, s,  8, 16);
    y += w2.y * __shfl_sync(mask, s,  9, 16);
    y += w2.z * __shfl_sync(mask, s, 10, 16);
    y += w2.w * __shfl_sync(mask, s, 11, 16);
    y += w3.x * __shfl_sync(mask, s, 12, 16);
    y += w3.y * __shfl_sync(mask, s, 13, 16);
    y += w3.z * __shfl_sync(mask, s, 14, 16);
    y += w3.w * __shfl_sync(mask, s, 15, 16);

    __stcs(out + gid, tanhf(y));
}

extern "C" void kernel_launch(void* const* d_in, const int* in_sizes, int n_in,
                              void* d_out, int out_size)
{
    // metadata order == setup_inputs order: values, idx, W, b
    const float* values = (const float*)d_in[0];
    const void*  idx    = d_in[1];
    const float* W      = (const float*)d_in[2];
    const float* bvec   = (const float*)d_in[3];
    float* out          = (float*)d_out;

    const int N = in_sizes[3] / 16;   // b has N*16 elements

    detect_idx_kernel<<<1, 1>>>((const unsigned int*)idx);

    const int threads = 256;
    const int total   = N * 16;
    const int blocks  = (total + threads - 1) / threads;
    weighted_atom_kernel<<<blocks, threads>>>(values, idx, W, bvec, out, N);
}